// round 2
// baseline (speedup 1.0000x reference)
#include <cuda_runtime.h>
#include <cstdint>

// VecArrayMultiplier54x54: exact {0,1} gate network == integer 54x54 multiply.
// out[row] = bits of (uint54(A[row]) * uint54(B[row])), LSB first, as 0/1 floats.
//
// R2: one warp per PAIR of rows.
//  - A-pair = 108 contiguous floats: lanes sweep [lane, 32+lane, 64+lane, 96+lane(<12)]
//    -> 4 coalesced LDG + 4 ballots yield both 54-bit operands (split at bit 54).
//  - Output: lane l (<27) extracts nibble 4l..4l+3 of the 108-bit product,
//    builds 4 float bit-patterns via (bit)*0x3F800000 (no I2F), 1 STG.128.

__device__ __forceinline__ uint4 nib_to_float4(uint64_t lo, uint64_t hi, int lane) {
    unsigned nib = (lane < 16) ? (unsigned)(lo >> (lane * 4))
                               : (unsigned)(hi >> ((lane - 16) * 4));
    uint4 v;
    v.x = ( nib        & 1u) * 0x3F800000u;
    v.y = ((nib >> 1)  & 1u) * 0x3F800000u;
    v.z = ((nib >> 2)  & 1u) * 0x3F800000u;
    v.w = ((nib >> 3)  & 1u) * 0x3F800000u;
    return v;
}

__global__ void mul54x54_pair_kernel(const float* __restrict__ A,
                                     const float* __restrict__ B,
                                     float* __restrict__ out,
                                     int batch) {
    const int pair = (int)((blockIdx.x * blockDim.x + threadIdx.x) >> 5);
    const int lane = threadIdx.x & 31;
    const int npairs_full = batch >> 1;
    const int nwarps = (batch + 1) >> 1;
    if (pair >= nwarps) return;

    if (pair < npairs_full) {
        const float* __restrict__ a = A + (size_t)pair * 108;
        const float* __restrict__ b = B + (size_t)pair * 108;

        float a0 = a[lane],        b0 = b[lane];
        float a1 = a[32 + lane],   b1 = b[32 + lane];
        float a2 = a[64 + lane],   b2 = b[64 + lane];
        float a3 = 0.0f,           b3 = 0.0f;
        if (lane < 12) { a3 = a[96 + lane]; b3 = b[96 + lane]; }

        unsigned ma0 = __ballot_sync(0xFFFFFFFFu, a0 > 0.5f);
        unsigned ma1 = __ballot_sync(0xFFFFFFFFu, a1 > 0.5f);
        unsigned ma2 = __ballot_sync(0xFFFFFFFFu, a2 > 0.5f);
        unsigned ma3 = __ballot_sync(0xFFFFFFFFu, a3 > 0.5f);
        unsigned mb0 = __ballot_sync(0xFFFFFFFFu, b0 > 0.5f);
        unsigned mb1 = __ballot_sync(0xFFFFFFFFu, b1 > 0.5f);
        unsigned mb2 = __ballot_sync(0xFFFFFFFFu, b2 > 0.5f);
        unsigned mb3 = __ballot_sync(0xFFFFFFFFu, b3 > 0.5f);

        // Split the 108-bit concatenated pair-stream at bit 54.
        const uint64_t av0 = (uint64_t)ma0 | ((uint64_t)(ma1 & 0x3FFFFFu) << 32);
        const uint64_t av1 = (uint64_t)(ma1 >> 22) | ((uint64_t)ma2 << 10)
                           | ((uint64_t)(ma3 & 0xFFFu) << 42);
        const uint64_t bv0 = (uint64_t)mb0 | ((uint64_t)(mb1 & 0x3FFFFFu) << 32);
        const uint64_t bv1 = (uint64_t)(mb1 >> 22) | ((uint64_t)mb2 << 10)
                           | ((uint64_t)(mb3 & 0xFFFu) << 42);

        const uint64_t p0lo = av0 * bv0;
        const uint64_t p0hi = __umul64hi(av0, bv0);
        const uint64_t p1lo = av1 * bv1;
        const uint64_t p1hi = __umul64hi(av1, bv1);

        if (lane < 27) {
            uint4* __restrict__ o = (uint4*)(out + (size_t)pair * 216);
            uint4 r0 = nib_to_float4(p0lo, p0hi, lane);
            uint4 r1 = nib_to_float4(p1lo, p1hi, lane);
            o[lane]      = r0;                 // row 2*pair   : bytes [0,432)
            o[27 + lane] = r1;                 // row 2*pair+1 : bytes [432,864)
        }
    } else {
        // Odd-batch tail: single row (not hit for batch=8192, kept for safety).
        const int row = 2 * pair;
        const float* __restrict__ a = A + (size_t)row * 54;
        const float* __restrict__ b = B + (size_t)row * 54;
        float a0 = a[lane], b0 = b[lane];
        float a1 = 0.0f, b1 = 0.0f;
        if (lane < 22) { a1 = a[32 + lane]; b1 = b[32 + lane]; }
        unsigned ma0 = __ballot_sync(0xFFFFFFFFu, a0 > 0.5f);
        unsigned ma1 = __ballot_sync(0xFFFFFFFFu, a1 > 0.5f);
        unsigned mb0 = __ballot_sync(0xFFFFFFFFu, b0 > 0.5f);
        unsigned mb1 = __ballot_sync(0xFFFFFFFFu, b1 > 0.5f);
        const uint64_t av = (uint64_t)ma0 | ((uint64_t)(ma1 & 0x3FFFFFu) << 32);
        const uint64_t bv = (uint64_t)mb0 | ((uint64_t)(mb1 & 0x3FFFFFu) << 32);
        const uint64_t lo = av * bv;
        const uint64_t hi = __umul64hi(av, bv);
        if (lane < 27) {
            uint4* __restrict__ o = (uint4*)(out + (size_t)row * 108);
            o[lane] = nib_to_float4(lo, hi, lane);
        }
    }
}

extern "C" void kernel_launch(void* const* d_in, const int* in_sizes, int n_in,
                              void* d_out, int out_size) {
    const float* A = (const float*)d_in[0];
    const float* B = (const float*)d_in[1];
    float* out = (float*)d_out;

    const int batch = in_sizes[0] / 54;              // 8192 expected
    const int nwarps = (batch + 1) >> 1;             // one warp per row-pair
    const int threads = 256;                         // 8 warps/block
    const int blocks = (nwarps + 7) / 8;

    mul54x54_pair_kernel<<<blocks, threads>>>(A, B, out, batch);
}